// round 13
// baseline (speedup 1.0000x reference)
#include <cuda_runtime.h>
#include <cstddef>

#define BATCH 16
#define NVERT 250000
#define NFACE 500000
#define MAXD  48                  // max adjacency entries per vertex
#define ROWH  32                  // floats per half-row: 24 used + 8 pad (128B aligned)

// ---------------------------------------------------------------------------
// Device scratch (static; no runtime allocation allowed)
// ---------------------------------------------------------------------------
__device__ int   g_deg[NVERT];
// Fixed-stride adjacency: row v at g_adjf[v*MAXD] (192B rows, 16B-aligned)
__device__ __align__(256) int g_adjf[(size_t)NVERT * MAXD + 8];       // 48 MB
// Two half-arrays: half h holds batches h*8..h*8+7, [v][32] floats,
// layout s(0..7): floats 3s..3s+2 = (x,y,z) of batch h*8+s. 128B rows.
__device__ __align__(256) float g_vh[(size_t)2 * NVERT * ROWH];       // 64 MB (48 used)
// gather output staged [v][b] for coalesced writes, 16 MB
__device__ float g_outvb[(size_t)NVERT * BATCH];

// ---------------------------------------------------------------------------
// 1. Zero degrees
// ---------------------------------------------------------------------------
__global__ void zero_deg_kernel() {
    int i = blockIdx.x * blockDim.x + threadIdx.x;
    if (i < NVERT) g_deg[i] = 0;
}

// ---------------------------------------------------------------------------
// 2. Fused count + fill: atomicAdd returns the slot; slots even -> int2 store
// ---------------------------------------------------------------------------
__global__ void fill_kernel(const int* __restrict__ faces) {
    int f = blockIdx.x * blockDim.x + threadIdx.x;
    if (f >= NFACE) return;
    int a = __ldg(&faces[3 * f + 0]);
    int b = __ldg(&faces[3 * f + 1]);
    int c = __ldg(&faces[3 * f + 2]);

    int pa = atomicAdd(&g_deg[a], 2);
    *reinterpret_cast<int2*>(&g_adjf[(size_t)a * MAXD + pa]) = make_int2(b, c);
    int pb = atomicAdd(&g_deg[b], 2);
    *reinterpret_cast<int2*>(&g_adjf[(size_t)b * MAXD + pb]) = make_int2(a, c);
    int pc = atomicAdd(&g_deg[c], 2);
    *reinterpret_cast<int2*>(&g_adjf[(size_t)c * MAXD + pc]) = make_int2(a, b);
}

// ---------------------------------------------------------------------------
// 3. SMEM-tiled transpose: vert [B][N][3] -> g_vh [2][N][32]
// ---------------------------------------------------------------------------
#define TVERTS 32
__global__ void __launch_bounds__(256)
transpose_kernel(const float* __restrict__ vert) {
    __shared__ float sm[BATCH][TVERTS * 3 + 1];
    int v0 = blockIdx.x * TVERTS;
    int nv = NVERT - v0;
    if (nv > TVERTS) nv = TVERTS;
    int nfl = nv * 3;

    for (int i = threadIdx.x; i < BATCH * TVERTS * 3; i += 256) {
        int b = i / (TVERTS * 3);
        int r = i % (TVERTS * 3);
        if (r < nfl) {
            sm[b][r] = vert[((size_t)b * NVERT + v0) * 3 + r];
        }
    }
    __syncthreads();

#pragma unroll
    for (int h = 0; h < 2; ++h) {
        float* dst = g_vh + ((size_t)h * NVERT + v0) * ROWH;
        for (int i = threadIdx.x; i < nv * ROWH; i += 256) {
            int vv = i >> 5;
            int rr = i & 31;
            if (rr < 24) {
                int s = rr / 3;
                int c = rr - 3 * s;
                dst[i] = sm[h * 8 + s][vv * 3 + c];
            }
        }
    }
}

// ---------------------------------------------------------------------------
// 4. Gather + finalize: one warp per (vertex, half); blockIdx.y = half.
//    Lane l: entry group e = l>>3 (0..3), chunk q = l&7 (active q<6).
//    4 entries per iteration: one broadcast int4 adjacency load (prefetched
//    one iteration ahead) + ONE LDG.128 instruction covering 4 aligned 128B
//    rows -> ~1.25 L1 wavefronts per entry.
// ---------------------------------------------------------------------------
__global__ void __launch_bounds__(256)
gather_kernel() {
    __shared__ float ssq[8][28];   // per-warp 24 sq values (+pad)

    int w = (blockIdx.x * blockDim.x + threadIdx.x) >> 5;
    if (w >= NVERT) return;
    int v = w;
    int half = blockIdx.y;
    const float* __restrict__ vbase = g_vh + (size_t)half * NVERT * ROWH;

    int warpIB = threadIdx.x >> 5;
    int lane = threadIdx.x & 31;
    int e = lane >> 3;           // entry within 4-group
    int q = lane & 7;            // float4 chunk within half-row
    bool act = (q < 6);
    unsigned foff = 4u * (unsigned)q;

    int d = g_deg[v];
    const int* __restrict__ adj = g_adjf + (size_t)v * MAXD;

    float a0 = 0.f, a1 = 0.f, a2 = 0.f, a3 = 0.f;

    int k = 0;
    int4 uu = make_int4(0, 0, 0, 0);
    if (d >= 4) uu = __ldg(reinterpret_cast<const int4*>(adj));   // broadcast

    while (k + 4 <= d) {
        int kn = k + 4;
        int4 un = (kn + 4 <= d) ? __ldg(reinterpret_cast<const int4*>(adj + kn)) : uu;
        int u = (e == 0) ? uu.x : (e == 1) ? uu.y : (e == 2) ? uu.z : uu.w;
        if (act) {
            float4 r = __ldg(reinterpret_cast<const float4*>(
                vbase + (((size_t)(unsigned)u) << 5) + foff));
            a0 += r.x;
            a1 += r.y;
            a2 += r.z;
            a3 += r.w;
        }
        uu = un;
        k = kn;
    }
    if (k < d) {   // 2 trailing entries (d is even)
        int2 t = __ldg(reinterpret_cast<const int2*>(adj + k));   // broadcast
        int u = (e == 1) ? t.y : t.x;
        if (act && e < 2) {
            float4 r = __ldg(reinterpret_cast<const float4*>(
                vbase + (((size_t)(unsigned)u) << 5) + foff));
            a0 += r.x;
            a1 += r.y;
            a2 += r.z;
            a3 += r.w;
        }
    }

    // combine the 4 e-groups (lanes with equal q)
    a0 += __shfl_xor_sync(0xffffffffu, a0, 8);
    a1 += __shfl_xor_sync(0xffffffffu, a1, 8);
    a2 += __shfl_xor_sync(0xffffffffu, a2, 8);
    a3 += __shfl_xor_sync(0xffffffffu, a3, 8);
    a0 += __shfl_xor_sync(0xffffffffu, a0, 16);
    a1 += __shfl_xor_sync(0xffffffffu, a1, 16);
    a2 += __shfl_xor_sync(0xffffffffu, a2, 16);
    a3 += __shfl_xor_sync(0xffffffffu, a3, 16);

    // finalize half-row floats 4q..4q+3, stage squared laplacian components
    if (e == 0 && act) {
        float inv = 1.0f / fmaxf((float)d, 1.0f);
        float4 pv = __ldg(reinterpret_cast<const float4*>(
            vbase + (((size_t)(unsigned)v) << 5) + foff));
        float l0 = a0 * inv - pv.x;
        float l1 = a1 * inv - pv.y;
        float l2 = a2 * inv - pv.z;
        float l3 = a3 * inv - pv.w;
        ssq[warpIB][foff + 0] = l0 * l0;
        ssq[warpIB][foff + 1] = l1 * l1;
        ssq[warpIB][foff + 2] = l2 * l2;
        ssq[warpIB][foff + 3] = l3 * l3;
    }
    __syncwarp();

    // per-slot reduce: batch = half*8 + s, s = lane (0..7)
    if (lane < 8) {
        int s = lane;
        float t = ssq[warpIB][3 * s] + ssq[warpIB][3 * s + 1] + ssq[warpIB][3 * s + 2];
        g_outvb[(size_t)v * BATCH + half * 8 + s] = sqrtf(t);   // 32B run per warp
    }
}

// ---------------------------------------------------------------------------
// 5. Output transpose: g_outvb [N][B] -> out [B][N], both sides coalesced.
// ---------------------------------------------------------------------------
#define OVERTS 64
__global__ void __launch_bounds__(256)
out_transpose_kernel(float* __restrict__ out) {
    __shared__ float sm[OVERTS][BATCH + 1];
    int v0 = blockIdx.x * OVERTS;
    int nv = NVERT - v0;
    if (nv > OVERTS) nv = OVERTS;

    for (int i = threadIdx.x; i < nv * BATCH; i += 256) {
        int vv = i >> 4;
        int b = i & 15;
        sm[vv][b] = g_outvb[(size_t)(v0 + vv) * BATCH + b];
    }
    __syncthreads();

    for (int i = threadIdx.x; i < BATCH * OVERTS; i += 256) {
        int b = i >> 6;
        int vv = i & 63;
        if (vv < nv) {
            out[(size_t)b * NVERT + (v0 + vv)] = sm[vv][b];
        }
    }
}

// ---------------------------------------------------------------------------
extern "C" void kernel_launch(void* const* d_in, const int* in_sizes, int n_in,
                              void* d_out, int out_size) {
    const float* vert = (const float*)d_in[0];
    const int* faces = (const int*)d_in[1];
    float* out = (float*)d_out;

    const int T = 256;

    zero_deg_kernel<<<(NVERT + T - 1) / T, T>>>();
    fill_kernel<<<(NFACE + T - 1) / T, T>>>(faces);

    transpose_kernel<<<(NVERT + TVERTS - 1) / TVERTS, T>>>(vert);

    {
        int warps_per_block = T / 32;  // 8
        dim3 grid((NVERT + warps_per_block - 1) / warps_per_block, 2);
        gather_kernel<<<grid, T>>>();
    }

    out_transpose_kernel<<<(NVERT + OVERTS - 1) / OVERTS, T>>>(out);
}

// round 14
// speedup vs baseline: 1.7030x; 1.7030x over previous
#include <cuda_runtime.h>
#include <cstddef>

#define BATCH 16
#define NVERT 250000
#define NFACE 500000
#define MAXD  64                  // max adjacency entries per vertex (r8-proven)

// ---------------------------------------------------------------------------
// Device scratch (static; no runtime allocation allowed)
// ---------------------------------------------------------------------------
__device__ int   g_deg[NVERT];
// Fixed-stride adjacency: row v at g_adjf[v*MAXD], 256B-aligned rows
__device__ __align__(256) int g_adjf[(size_t)NVERT * MAXD];           // 64 MB
// [v][48]: b0(x,y,z) ... b15(x,y,z). 192B rows.
__device__ __align__(256) float g_vert3[(size_t)NVERT * BATCH * 3];   // 48 MB
// gather output staged [v][b] for coalesced writes, 16 MB
__device__ float g_outvb[(size_t)NVERT * BATCH];

// ---------------------------------------------------------------------------
// 1. Zero degrees
// ---------------------------------------------------------------------------
__global__ void zero_deg_kernel() {
    int i = blockIdx.x * blockDim.x + threadIdx.x;
    if (i < NVERT) g_deg[i] = 0;
}

// ---------------------------------------------------------------------------
// 2. FUSED prep kernel: grid-partitioned transpose + fill.
//    Blocks [0, TBLKS) transpose vert [B][N][3] -> g_vert3 [N][48];
//    blocks [TBLKS, TBLKS+FBLKS) build the adjacency (fused count+fill).
//    The two halves touch disjoint data; their bottlenecks (DRAM streaming
//    vs L2-atomic latency) overlap on the chip.
// ---------------------------------------------------------------------------
#define TVERTS 32
#define TBLKS ((NVERT + TVERTS - 1) / TVERTS)      // 7813
#define FBLKS ((NFACE + 255) / 256)                // 1954

__global__ void __launch_bounds__(256)
prep_kernel(const float* __restrict__ vert, const int* __restrict__ faces) {
    if (blockIdx.x < TBLKS) {
        // ---- transpose part ----
        __shared__ float sm[BATCH][TVERTS * 3 + 1];
        int v0 = blockIdx.x * TVERTS;
        int nv = NVERT - v0;
        if (nv > TVERTS) nv = TVERTS;
        int nfl = nv * 3;

        for (int i = threadIdx.x; i < BATCH * TVERTS * 3; i += 256) {
            int b = i / (TVERTS * 3);
            int r = i % (TVERTS * 3);
            if (r < nfl) {
                sm[b][r] = vert[((size_t)b * NVERT + v0) * 3 + r];
            }
        }
        __syncthreads();

        float* dst = g_vert3 + (size_t)v0 * (BATCH * 3);
        for (int i = threadIdx.x; i < nv * BATCH * 3; i += 256) {
            int vv = i / (BATCH * 3);
            int r = i % (BATCH * 3);
            int b = r / 3;
            int c = r % 3;
            dst[i] = sm[b][vv * 3 + c];
        }
    } else {
        // ---- fill part (fused count+fill; slots even -> aligned int2) ----
        int f = (blockIdx.x - TBLKS) * blockDim.x + threadIdx.x;
        if (f >= NFACE) return;
        int a = __ldg(&faces[3 * f + 0]);
        int b = __ldg(&faces[3 * f + 1]);
        int c = __ldg(&faces[3 * f + 2]);

        int pa = atomicAdd(&g_deg[a], 2);
        *reinterpret_cast<int2*>(&g_adjf[(size_t)a * MAXD + pa]) = make_int2(b, c);
        int pb = atomicAdd(&g_deg[b], 2);
        *reinterpret_cast<int2*>(&g_adjf[(size_t)b * MAXD + pb]) = make_int2(a, c);
        int pc = atomicAdd(&g_deg[c], 2);
        *reinterpret_cast<int2*>(&g_adjf[(size_t)c * MAXD + pc]) = make_int2(a, b);
    }
}

// ---------------------------------------------------------------------------
// 3. Gather + finalize (exact round-8 structure): one warp per vertex,
//    independent warps. lane l: batch b = l&15, parity j = l>>4; half-warp
//    per neighbor 192B row, adjacency prefetched one iteration ahead.
//    Output written coalesced to g_outvb (64B run per warp).
// ---------------------------------------------------------------------------
__global__ void __launch_bounds__(256)
gather_kernel() {
    int w = (blockIdx.x * blockDim.x + threadIdx.x) >> 5;
    if (w >= NVERT) return;
    int v = w;
    int lane = threadIdx.x & 31;
    int b = lane & 15;
    int j = lane >> 4;

    int d = g_deg[v];

    float ax = 0.f, ay = 0.f, az = 0.f;
    const int* __restrict__ adj = g_adjf + (size_t)v * MAXD;

    int k = j;
    int u = (k < d) ? __ldg(&adj[k]) : 0;
    while (k < d) {
        int k2 = k + 2;
        int u_next = (k2 < d) ? __ldg(&adj[k2]) : 0;   // prefetch: breaks chain
        const float* __restrict__ p = g_vert3 + ((size_t)u * (BATCH * 3) + b * 3);
        ax += __ldg(&p[0]);
        ay += __ldg(&p[1]);
        az += __ldg(&p[2]);
        u = u_next;
        k = k2;
    }

    ax += __shfl_xor_sync(0xffffffffu, ax, 16);
    ay += __shfl_xor_sync(0xffffffffu, ay, 16);
    az += __shfl_xor_sync(0xffffffffu, az, 16);

    if (j == 0) {
        float inv = 1.0f / fmaxf((float)d, 1.0f);
        const float* __restrict__ p = g_vert3 + ((size_t)v * (BATCH * 3) + b * 3);
        float lx = ax * inv - p[0];
        float ly = ay * inv - p[1];
        float lz = az * inv - p[2];
        // coalesced: lanes 0..15 write 16 consecutive floats (64B run)
        g_outvb[(size_t)v * BATCH + b] = sqrtf(lx * lx + ly * ly + lz * lz);
    }
}

// ---------------------------------------------------------------------------
// 4. Output transpose: g_outvb [N][B] -> out [B][N], both sides coalesced.
// ---------------------------------------------------------------------------
#define OVERTS 64
__global__ void __launch_bounds__(256)
out_transpose_kernel(float* __restrict__ out) {
    __shared__ float sm[OVERTS][BATCH + 1];
    int v0 = blockIdx.x * OVERTS;
    int nv = NVERT - v0;
    if (nv > OVERTS) nv = OVERTS;

    for (int i = threadIdx.x; i < nv * BATCH; i += 256) {
        int vv = i >> 4;
        int b = i & 15;
        sm[vv][b] = g_outvb[(size_t)(v0 + vv) * BATCH + b];
    }
    __syncthreads();

    for (int i = threadIdx.x; i < BATCH * OVERTS; i += 256) {
        int b = i >> 6;
        int vv = i & 63;
        if (vv < nv) {
            out[(size_t)b * NVERT + (v0 + vv)] = sm[vv][b];
        }
    }
}

// ---------------------------------------------------------------------------
extern "C" void kernel_launch(void* const* d_in, const int* in_sizes, int n_in,
                              void* d_out, int out_size) {
    const float* vert = (const float*)d_in[0];
    const int* faces = (const int*)d_in[1];
    float* out = (float*)d_out;

    const int T = 256;

    zero_deg_kernel<<<(NVERT + T - 1) / T, T>>>();

    // fused transpose + adjacency build (independent halves overlap)
    prep_kernel<<<TBLKS + FBLKS, T>>>(vert, faces);

    {
        int warps_per_block = T / 32;  // 8
        int blocks = (NVERT + warps_per_block - 1) / warps_per_block;
        gather_kernel<<<blocks, T>>>();
    }

    out_transpose_kernel<<<(NVERT + OVERTS - 1) / OVERTS, T>>>(out);
}